// round 10
// baseline (speedup 1.0000x reference)
#include <cuda_runtime.h>
#include <cuda_fp16.h>
#include <cstdint>

// ---------------------------------------------------------------------------
// GCN_simple: layer3+meanpool collapse analytically; layers 1-2 are dense
// GEMMs (identity propagation except graph 0, fixed by parallel fixups).
// mma.sync HMMA pipeline (tcgen05 rejected by compute_103 virtual target).
// R9: gemm1 converts fp32 x in the stage-load path (LDG->cvt->STS), killing
// the standalone conv_x kernel; 512-thread CTAs, 32x32 warp tiles.
// ---------------------------------------------------------------------------

#define NROWS 65536      // BATCH * N_NODES
#define KDIM  512
#define NDIM  512
#define NGRAPH 512
#define GSIZE  128
#define OUTD   10

#define BM 128
#define BN 128
#define BK 64
#define KTILES (KDIM / BK)   // 8
#define ALD 72               // smem row pitch in halves (64 + 8 pad)

#define ABYTES (BM * ALD * 2)        // 18432
#define BBYTES (BN * ALD * 2)        // 18432
#define STB (ABYTES + BBYTES)        // 36864
#define SMEM_TOTAL (3 * STB)         // 110592

#define NTHREADS 512

// ------------------------------- device scratch -----------------------------
__device__ __half g_H1[(size_t)NROWS * KDIM];
__device__ __half g_W1t[KDIM * NDIM];   // W1^T: [n][k] fp16
__device__ __half g_W2t[KDIM * NDIM];
__device__ float  g_pool[NGRAPH * NDIM];
__device__ float  g_L1[GSIZE * NDIM];
__device__ float  g_L2[GSIZE * NDIM];
__device__ float  g_Wc[KDIM * OUTD];
__device__ float  g_bc[OUTD];

// ------------------------------- helpers ------------------------------------
__device__ __forceinline__ void cpasync16(void* smem_ptr, const void* gmem_ptr) {
    uint32_t s = (uint32_t)__cvta_generic_to_shared(smem_ptr);
    asm volatile("cp.async.cg.shared.global [%0], [%1], 16;\n" :: "r"(s), "l"(gmem_ptr));
}
__device__ __forceinline__ void cp_commit() {
    asm volatile("cp.async.commit_group;\n" ::: "memory");
}
__device__ __forceinline__ void cp_wait1() {
    asm volatile("cp.async.wait_group 1;\n" ::: "memory");
}
__device__ __forceinline__ void mma16816(float& c0, float& c1, float& c2, float& c3,
                                         uint32_t a0, uint32_t a1, uint32_t a2, uint32_t a3,
                                         uint32_t b0, uint32_t b1) {
    asm volatile(
        "mma.sync.aligned.m16n8k16.row.col.f32.f16.f16.f32 "
        "{%0,%1,%2,%3}, {%4,%5,%6,%7}, {%8,%9}, {%0,%1,%2,%3};\n"
        : "+f"(c0), "+f"(c1), "+f"(c2), "+f"(c3)
        : "r"(a0), "r"(a1), "r"(a2), "r"(a3), "r"(b0), "r"(b1));
}
__device__ __forceinline__ void ldsm_x4(uint32_t& r0, uint32_t& r1, uint32_t& r2, uint32_t& r3,
                                        uint32_t saddr) {
    asm volatile("ldmatrix.sync.aligned.m8n8.x4.shared.b16 {%0,%1,%2,%3}, [%4];"
                 : "=r"(r0), "=r"(r1), "=r"(r2), "=r"(r3) : "r"(saddr));
}
__device__ __forceinline__ uint32_t smem_u32(const void* p) {
    return (uint32_t)__cvta_generic_to_shared(p);
}
__device__ __forceinline__ uint32_t h2pack(float lo, float hi) {
    __half2 h = __floats2half2_rn(lo, hi);
    return *reinterpret_cast<uint32_t*>(&h);
}

// ------------------------------- setup kernels ------------------------------
// out[n][k] = (half) W[k][n]; blockIdx.z selects W1/W2.
__global__ void convT_w_kernel(const float* __restrict__ W1, const float* __restrict__ W2) {
    __shared__ float t[32][33];
    const float* W = blockIdx.z ? W2 : W1;
    __half* out = blockIdx.z ? g_W2t : g_W1t;
    int bx = blockIdx.x * 32, by = blockIdx.y * 32;
    #pragma unroll
    for (int i = 0; i < 32; i += 8)
        t[threadIdx.y + i][threadIdx.x] = W[(size_t)(by + threadIdx.y + i) * NDIM + bx + threadIdx.x];
    __syncthreads();
    #pragma unroll
    for (int i = 0; i < 32; i += 8)
        out[(size_t)(bx + threadIdx.y + i) * KDIM + by + threadIdx.x] =
            __float2half(t[threadIdx.x][threadIdx.y + i]);
}

__global__ void wc_kernel(const float* __restrict__ W3, const float* __restrict__ Wlin) {
    int k = blockIdx.x, c = threadIdx.x >> 5, lane = threadIdx.x & 31;
    float a = 0.f;
    for (int j = lane; j < KDIM; j += 32) a += W3[k * KDIM + j] * Wlin[j * OUTD + c];
    #pragma unroll
    for (int o = 16; o; o >>= 1) a += __shfl_xor_sync(0xffffffffu, a, o);
    if (lane == 0) g_Wc[k * OUTD + c] = a;
}

__global__ void bc_kernel(const float* __restrict__ b3, const float* __restrict__ Wlin,
                          const float* __restrict__ blin) {
    int c = threadIdx.x >> 5, lane = threadIdx.x & 31;
    float a = 0.f;
    for (int k = lane; k < KDIM; k += 32) a += b3[k] * Wlin[k * OUTD + c];
    #pragma unroll
    for (int o = 16; o; o >>= 1) a += __shfl_xor_sync(0xffffffffu, a, o);
    if (lane == 0) g_bc[c] = a + blin[c];
}

// ------------------------------- main GEMMs ---------------------------------
// 512 threads, 16 warps as 4x4 grid of 32x32 warp tiles over 128x128 CTA tile.
// MODE 1: H1 = relu(x(fp32) @ W1 + b1); A converted fp32->fp16 in stage load;
//         mtile 0 raw acc -> g_L1.
// MODE 2: pool[g] = colsum(relu(H1 @ W2 + b2)); mtile 0 raw acc -> g_L2.
template <int MODE>
__global__ void __launch_bounds__(NTHREADS, 2) gemm_kernel(const float* __restrict__ xA,
                                                           const float* __restrict__ bias) {
    extern __shared__ char smem[];
    const int tid  = threadIdx.x;
    const int lane = tid & 31;
    const int warp = tid >> 5;
    const int wm = warp >> 2;                // 0..3  (32-row strip)
    const int wn = warp & 3;                 // 0..3  (32-col strip)
    const int ntile = blockIdx.x;
    const int mtile = blockIdx.y;
    const size_t mbase = (size_t)mtile * BM;
    const int nbase = ntile * BN;

    const __half* __restrict__ Bt = (MODE == 1) ? g_W1t : g_W2t;

    float acc[2][4][4];
    #pragma unroll
    for (int a = 0; a < 2; ++a)
        #pragma unroll
        for (int b = 0; b < 4; ++b)
            #pragma unroll
            for (int c = 0; c < 4; ++c) acc[a][b][c] = 0.f;

    const int lrow = lane & 15;              // ldmatrix row-select
    const int lkof = (lane >> 4) * 8;        // 0 or 8 halves

    auto load_stage = [&](int s, int kt) {
        const int k0 = kt * BK;
        char* as = smem + s * STB;
        char* bs = as + ABYTES;
        if (MODE == 1) {
            // A: LDG fp32 -> cvt -> STS fp16. 128 rows x 8 chunks of 8 halves.
            #pragma unroll
            for (int i = 0; i < 2; ++i) {
                int id = tid + NTHREADS * i;
                int row = id >> 3, ch = id & 7;
                const float4* src = reinterpret_cast<const float4*>(
                    xA + (mbase + row) * KDIM + k0 + ch * 8);
                float4 v0 = src[0];
                float4 v1 = src[1];
                *reinterpret_cast<uint4*>(as + (row * ALD + ch * 8) * 2) =
                    make_uint4(h2pack(v0.x, v0.y), h2pack(v0.z, v0.w),
                               h2pack(v1.x, v1.y), h2pack(v1.z, v1.w));
            }
        } else {
            #pragma unroll
            for (int i = 0; i < 2; ++i) {
                int id = tid + NTHREADS * i;
                int row = id >> 3, ch = id & 7;
                cpasync16(as + (row * ALD + ch * 8) * 2,
                          g_H1 + (mbase + row) * KDIM + k0 + ch * 8);
            }
        }
        #pragma unroll
        for (int i = 0; i < 2; ++i) {
            int id = tid + NTHREADS * i;
            int row = id >> 3, ch = id & 7;
            cpasync16(bs + (row * ALD + ch * 8) * 2,
                      Bt + (size_t)(nbase + row) * KDIM + k0 + ch * 8);
        }
    };

    auto compute = [&](int s) {
        const char* as = smem + s * STB;
        const uint32_t a_u32 = smem_u32(as);
        const uint32_t b_u32 = a_u32 + ABYTES;
        #pragma unroll
        for (int ks = 0; ks < 4; ++ks) {
            const int kh = ks * 16;
            uint32_t af[2][4];
            #pragma unroll
            for (int mi = 0; mi < 2; ++mi) {
                int row = wm * 32 + mi * 16 + lrow;
                ldsm_x4(af[mi][0], af[mi][1], af[mi][2], af[mi][3],
                        a_u32 + (row * ALD + kh + lkof) * 2);
            }
            uint32_t bf[4][2];
            #pragma unroll
            for (int np = 0; np < 2; ++np) {
                int row = wn * 32 + np * 16 + lrow;
                ldsm_x4(bf[2 * np][0], bf[2 * np + 1][0],
                        bf[2 * np][1], bf[2 * np + 1][1],
                        b_u32 + (row * ALD + kh + lkof) * 2);
            }
            #pragma unroll
            for (int mi = 0; mi < 2; ++mi)
                #pragma unroll
                for (int ni = 0; ni < 4; ++ni)
                    mma16816(acc[mi][ni][0], acc[mi][ni][1], acc[mi][ni][2], acc[mi][ni][3],
                             af[mi][0], af[mi][1], af[mi][2], af[mi][3],
                             bf[ni][0], bf[ni][1]);
        }
    };

    load_stage(0, 0); cp_commit();
    load_stage(1, 1); cp_commit();

    #pragma unroll
    for (int kt = 0; kt < KTILES; ++kt) {
        cp_wait1();
        __syncthreads();
        if (kt + 2 < KTILES) load_stage((kt + 2) % 3, kt + 2);
        cp_commit();
        compute(kt % 3);
    }

    // ------------------------------ epilogue --------------------------------
    if (MODE == 1) {
        #pragma unroll
        for (int mi = 0; mi < 2; ++mi) {
            int r0 = wm * 32 + mi * 16 + (lane >> 2);
            #pragma unroll
            for (int ni = 0; ni < 4; ++ni) {
                int c0 = wn * 32 + ni * 8 + ((lane & 3) << 1);
                int gc = nbase + c0;
                if (mtile == 0) {
                    g_L1[r0 * NDIM + gc]           = acc[mi][ni][0];
                    g_L1[r0 * NDIM + gc + 1]       = acc[mi][ni][1];
                    g_L1[(r0 + 8) * NDIM + gc]     = acc[mi][ni][2];
                    g_L1[(r0 + 8) * NDIM + gc + 1] = acc[mi][ni][3];
                }
                float bb0 = bias[gc], bb1 = bias[gc + 1];
                float v0 = fmaxf(acc[mi][ni][0] + bb0, 0.f);
                float v1 = fmaxf(acc[mi][ni][1] + bb1, 0.f);
                float v2 = fmaxf(acc[mi][ni][2] + bb0, 0.f);
                float v3 = fmaxf(acc[mi][ni][3] + bb1, 0.f);
                *reinterpret_cast<__half2*>(g_H1 + (mbase + r0) * NDIM + gc)     = __floats2half2_rn(v0, v1);
                *reinterpret_cast<__half2*>(g_H1 + (mbase + r0 + 8) * NDIM + gc) = __floats2half2_rn(v2, v3);
            }
        }
    } else {
        float cs0[4], cs1[4];
        #pragma unroll
        for (int ni = 0; ni < 4; ++ni) { cs0[ni] = 0.f; cs1[ni] = 0.f; }
        #pragma unroll
        for (int mi = 0; mi < 2; ++mi) {
            int r0 = wm * 32 + mi * 16 + (lane >> 2);
            #pragma unroll
            for (int ni = 0; ni < 4; ++ni) {
                int c0 = wn * 32 + ni * 8 + ((lane & 3) << 1);
                int gc = nbase + c0;
                if (mtile == 0) {
                    g_L2[r0 * NDIM + gc]           = acc[mi][ni][0];
                    g_L2[r0 * NDIM + gc + 1]       = acc[mi][ni][1];
                    g_L2[(r0 + 8) * NDIM + gc]     = acc[mi][ni][2];
                    g_L2[(r0 + 8) * NDIM + gc + 1] = acc[mi][ni][3];
                }
                float bb0 = bias[gc], bb1 = bias[gc + 1];
                cs0[ni] += fmaxf(acc[mi][ni][0] + bb0, 0.f) + fmaxf(acc[mi][ni][2] + bb0, 0.f);
                cs1[ni] += fmaxf(acc[mi][ni][1] + bb1, 0.f) + fmaxf(acc[mi][ni][3] + bb1, 0.f);
            }
        }
        // reduce over the 8 lanes sharing (lane & 3): sums this warp's 32 rows
        #pragma unroll
        for (int ni = 0; ni < 4; ++ni) {
            #pragma unroll
            for (int o = 4; o <= 16; o <<= 1) {
                cs0[ni] += __shfl_xor_sync(0xffffffffu, cs0[ni], o);
                cs1[ni] += __shfl_xor_sync(0xffffffffu, cs1[ni], o);
            }
        }
        __syncthreads();
        float* cs = reinterpret_cast<float*>(smem);
        if (tid < BN) cs[tid] = 0.f;
        __syncthreads();
        if ((lane >> 2) == 0) {           // lanes 0..3: 4 wm-warps add into each column
            #pragma unroll
            for (int ni = 0; ni < 4; ++ni) {
                int c0 = wn * 32 + ni * 8 + ((lane & 3) << 1);
                atomicAdd(&cs[c0],     cs0[ni]);
                atomicAdd(&cs[c0 + 1], cs1[ni]);
            }
        }
        __syncthreads();
        if (tid < BN) g_pool[(size_t)mtile * NDIM + nbase + tid] = cs[tid];
    }
}

// ------------------------------- graph-0 fixups (parallel) ------------------
__global__ void fixup1_kernel(const float* __restrict__ b1) {
    int c = blockIdx.x;                  // 512 columns
    int r = threadIdx.x;                 // 128 rows
    float v = g_L1[r * NDIM + c];
    __shared__ float sred[4];
    float s = v;
    #pragma unroll
    for (int o = 16; o; o >>= 1) s += __shfl_xor_sync(0xffffffffu, s, o);
    if ((r & 31) == 0) sred[r >> 5] = s;
    __syncthreads();
    float S = sred[0] + sred[1] + sred[2] + sred[3];
    float out = (S + v) * (1.f / 129.f) + b1[c];
    g_H1[(size_t)r * NDIM + c] = __float2half(out > 0.f ? out : 0.f);
}

__global__ void fixup2_kernel(const float* __restrict__ b2) {
    int c = blockIdx.x;
    int r = threadIdx.x;
    float v = g_L2[r * NDIM + c];
    __shared__ float sred[4];
    float s = v;
    #pragma unroll
    for (int o = 16; o; o >>= 1) s += __shfl_xor_sync(0xffffffffu, s, o);
    if ((r & 31) == 0) sred[r >> 5] = s;
    __syncthreads();
    float S = sred[0] + sred[1] + sred[2] + sred[3];
    float val = (S + v) * (1.f / 129.f) + b2[c];
    float rel = val > 0.f ? val : 0.f;
    #pragma unroll
    for (int o = 16; o; o >>= 1) rel += __shfl_xor_sync(0xffffffffu, rel, o);
    if ((r & 31) == 0) sred[r >> 5] = rel;
    __syncthreads();
    if (r == 0) g_pool[c] = sred[0] + sred[1] + sred[2] + sred[3];
}

// ------------------------------- final projection ---------------------------
__global__ void final_kernel(float* __restrict__ out) {
    int g = blockIdx.x, c = threadIdx.x >> 5, lane = threadIdx.x & 31;
    float a = 0.f;
    for (int k = lane; k < KDIM; k += 32)
        a += g_pool[(size_t)g * NDIM + k] * g_Wc[k * OUTD + c];
    #pragma unroll
    for (int o = 16; o; o >>= 1) a += __shfl_xor_sync(0xffffffffu, a, o);
    if (lane == 0) out[g * OUTD + c] = a * (1.f / (float)GSIZE) + g_bc[c];
}

// ------------------------------- launch -------------------------------------
extern "C" void kernel_launch(void* const* d_in, const int* in_sizes, int n_in,
                              void* d_out, int out_size) {
    const float* x    = (const float*)d_in[0];
    const float* W1   = (const float*)d_in[1];
    const float* b1   = (const float*)d_in[2];
    const float* W2   = (const float*)d_in[3];
    const float* b2   = (const float*)d_in[4];
    const float* W3   = (const float*)d_in[5];
    const float* b3   = (const float*)d_in[6];
    const float* Wlin = (const float*)d_in[7];
    const float* blin = (const float*)d_in[8];
    float* out = (float*)d_out;

    cudaFuncSetAttribute(gemm_kernel<1>, cudaFuncAttributeMaxDynamicSharedMemorySize, SMEM_TOTAL);
    cudaFuncSetAttribute(gemm_kernel<2>, cudaFuncAttributeMaxDynamicSharedMemorySize, SMEM_TOTAL);

    dim3 grid(NDIM / BN, NROWS / BM);    // (4, 512)

    convT_w_kernel<<<dim3(16, 16, 2), dim3(32, 8)>>>(W1, W2);               // 1
    gemm_kernel<1><<<grid, NTHREADS, SMEM_TOTAL>>>(x, b1);                  // 2
    fixup1_kernel<<<NDIM, GSIZE>>>(b1);                                     // 3
    wc_kernel<<<KDIM, 320>>>(W3, Wlin);                                     // 4
    bc_kernel<<<1, 320>>>(b3, Wlin, blin);                                  // 5
    gemm_kernel<2><<<grid, NTHREADS, SMEM_TOTAL>>>(nullptr, b2);            // 6  <- ncu
    fixup2_kernel<<<NDIM, GSIZE>>>(b2);                                     // 7
    final_kernel<<<NGRAPH, 320>>>(out);                                     // 8
}

// round 13
// speedup vs baseline: 1.0886x; 1.0886x over previous
#include <cuda_runtime.h>
#include <cuda_fp16.h>
#include <cstdint>

// ---------------------------------------------------------------------------
// GCN_simple: layer3+meanpool collapse analytically; layers 1-2 are dense
// GEMMs (identity propagation except graph 0, fixed by parallel fixups).
// mma.sync HMMA pipeline (tcgen05 rejected by compute_103 virtual target).
// R10: gemms identical to R8 (best: 299.7us). Standalone conv_x restored
// (R9's fused LDG->STS regressed 58% - blocking loads break the cp.async
// pipeline). Small kernels rewritten: smem-staged Wlin/Wc (coalesced), wc+bc
// merged, final batched 4 graphs/block.
// ---------------------------------------------------------------------------

#define NROWS 65536      // BATCH * N_NODES
#define KDIM  512
#define NDIM  512
#define NGRAPH 512
#define GSIZE  128
#define OUTD   10

#define BM 128
#define BN 128
#define BK 64
#define KTILES (KDIM / BK)   // 8
#define ALD 72               // smem row pitch in halves (64 + 8 pad)

#define ABYTES (BM * ALD * 2)        // 18432
#define BBYTES (BN * ALD * 2)        // 18432
#define STB (ABYTES + BBYTES)        // 36864
#define SMEM_TOTAL (3 * STB)         // 110592

#define NTHREADS 512

// ------------------------------- device scratch -----------------------------
__device__ __half g_Xh[(size_t)NROWS * KDIM];
__device__ __half g_H1[(size_t)NROWS * KDIM];
__device__ __half g_W1t[KDIM * NDIM];   // W1^T: [n][k] fp16
__device__ __half g_W2t[KDIM * NDIM];
__device__ float  g_pool[NGRAPH * NDIM];
__device__ float  g_L1[GSIZE * NDIM];
__device__ float  g_L2[GSIZE * NDIM];
__device__ float  g_Wc[KDIM * OUTD];
__device__ float  g_bc[OUTD];

// ------------------------------- helpers ------------------------------------
__device__ __forceinline__ void cpasync16(void* smem_ptr, const void* gmem_ptr) {
    uint32_t s = (uint32_t)__cvta_generic_to_shared(smem_ptr);
    asm volatile("cp.async.cg.shared.global [%0], [%1], 16;\n" :: "r"(s), "l"(gmem_ptr));
}
__device__ __forceinline__ void cp_commit() {
    asm volatile("cp.async.commit_group;\n" ::: "memory");
}
__device__ __forceinline__ void cp_wait1() {
    asm volatile("cp.async.wait_group 1;\n" ::: "memory");
}
__device__ __forceinline__ void mma16816(float& c0, float& c1, float& c2, float& c3,
                                         uint32_t a0, uint32_t a1, uint32_t a2, uint32_t a3,
                                         uint32_t b0, uint32_t b1) {
    asm volatile(
        "mma.sync.aligned.m16n8k16.row.col.f32.f16.f16.f32 "
        "{%0,%1,%2,%3}, {%4,%5,%6,%7}, {%8,%9}, {%0,%1,%2,%3};\n"
        : "+f"(c0), "+f"(c1), "+f"(c2), "+f"(c3)
        : "r"(a0), "r"(a1), "r"(a2), "r"(a3), "r"(b0), "r"(b1));
}
__device__ __forceinline__ void ldsm_x4(uint32_t& r0, uint32_t& r1, uint32_t& r2, uint32_t& r3,
                                        uint32_t saddr) {
    asm volatile("ldmatrix.sync.aligned.m8n8.x4.shared.b16 {%0,%1,%2,%3}, [%4];"
                 : "=r"(r0), "=r"(r1), "=r"(r2), "=r"(r3) : "r"(saddr));
}
__device__ __forceinline__ uint32_t smem_u32(const void* p) {
    return (uint32_t)__cvta_generic_to_shared(p);
}

// ------------------------------- setup kernels ------------------------------
__global__ void conv_x_kernel(const float* __restrict__ x) {
    size_t i = ((size_t)blockIdx.x * blockDim.x + threadIdx.x) * 8;
    float4 v0 = *reinterpret_cast<const float4*>(x + i);
    float4 v1 = *reinterpret_cast<const float4*>(x + i + 4);
    __half2 h0 = __floats2half2_rn(v0.x, v0.y);
    __half2 h1 = __floats2half2_rn(v0.z, v0.w);
    __half2 h2 = __floats2half2_rn(v1.x, v1.y);
    __half2 h3 = __floats2half2_rn(v1.z, v1.w);
    uint4 packed = make_uint4(*reinterpret_cast<uint32_t*>(&h0), *reinterpret_cast<uint32_t*>(&h1),
                              *reinterpret_cast<uint32_t*>(&h2), *reinterpret_cast<uint32_t*>(&h3));
    *reinterpret_cast<uint4*>(g_Xh + i) = packed;
}

// out[n][k] = (half) W[k][n]; blockIdx.z selects W1/W2.
__global__ void convT_w_kernel(const float* __restrict__ W1, const float* __restrict__ W2) {
    __shared__ float t[32][33];
    const float* W = blockIdx.z ? W2 : W1;
    __half* out = blockIdx.z ? g_W2t : g_W1t;
    int bx = blockIdx.x * 32, by = blockIdx.y * 32;
    #pragma unroll
    for (int i = 0; i < 32; i += 8)
        t[threadIdx.y + i][threadIdx.x] = W[(size_t)(by + threadIdx.y + i) * NDIM + bx + threadIdx.x];
    __syncthreads();
    #pragma unroll
    for (int i = 0; i < 32; i += 8)
        out[(size_t)(bx + threadIdx.y + i) * KDIM + by + threadIdx.x] =
            __float2half(t[threadIdx.x][threadIdx.y + i]);
}

// Blocks 0..63: Wc[k][c] = sum_j W3[k][j]*Wlin[j][c] for 8 k-rows per block.
// Block 64:    bc[c] = sum_j b3[j]*Wlin[j][c] + blin[c].
__global__ void wcbc_kernel(const float* __restrict__ W3, const float* __restrict__ Wlin,
                            const float* __restrict__ b3, const float* __restrict__ blin) {
    __shared__ float wl[KDIM * OUTD];    // 20 KB, coalesced load
    int tid = threadIdx.x;
    for (int i = tid; i < KDIM * OUTD; i += 256) wl[i] = Wlin[i];
    __syncthreads();
    int warp = tid >> 5, lane = tid & 31;
    if (blockIdx.x < 64) {
        int k = blockIdx.x * 8 + warp;
        float acc[OUTD];
        #pragma unroll
        for (int c = 0; c < OUTD; ++c) acc[c] = 0.f;
        for (int j = lane; j < KDIM; j += 32) {
            float a = W3[(size_t)k * KDIM + j];
            #pragma unroll
            for (int c = 0; c < OUTD; ++c) acc[c] += a * wl[j * OUTD + c];
        }
        #pragma unroll
        for (int c = 0; c < OUTD; ++c)
            #pragma unroll
            for (int o = 16; o; o >>= 1) acc[c] += __shfl_xor_sync(0xffffffffu, acc[c], o);
        if (lane < OUTD) g_Wc[k * OUTD + lane] = acc[lane];   // lane i holds acc[i]? no:
        // each lane has the full reduced acc[]; use lane 0..9 to write c = lane.
        // (acc[] identical on all lanes after xor-reduction)
    } else if (warp == 0) {
        float acc[OUTD];
        #pragma unroll
        for (int c = 0; c < OUTD; ++c) acc[c] = 0.f;
        for (int j = lane; j < KDIM; j += 32) {
            float a = b3[j];
            #pragma unroll
            for (int c = 0; c < OUTD; ++c) acc[c] += a * wl[j * OUTD + c];
        }
        #pragma unroll
        for (int c = 0; c < OUTD; ++c)
            #pragma unroll
            for (int o = 16; o; o >>= 1) acc[c] += __shfl_xor_sync(0xffffffffu, acc[c], o);
        if (lane < OUTD) g_bc[lane] = acc[lane] + blin[lane];
    }
}

// ------------------------------- main GEMMs (R8-proven) ---------------------
// 512 threads, 16 warps as 4x4 grid of 32x32 warp tiles over 128x128 CTA tile.
// MODE 1: H1 = relu(Xh @ W1 + b1); mtile 0 raw acc -> g_L1.
// MODE 2: pool[g] = colsum(relu(H1 @ W2 + b2)); mtile 0 raw acc -> g_L2.
template <int MODE>
__global__ void __launch_bounds__(NTHREADS, 2) gemm_kernel(const float* __restrict__ bias) {
    extern __shared__ char smem[];
    const int tid  = threadIdx.x;
    const int lane = tid & 31;
    const int warp = tid >> 5;
    const int wm = warp >> 2;                // 0..3  (32-row strip)
    const int wn = warp & 3;                 // 0..3  (32-col strip)
    const int ntile = blockIdx.x;
    const int mtile = blockIdx.y;
    const size_t mbase = (size_t)mtile * BM;
    const int nbase = ntile * BN;

    const __half* __restrict__ A  = (MODE == 1) ? g_Xh  : g_H1;
    const __half* __restrict__ Bt = (MODE == 1) ? g_W1t : g_W2t;

    float acc[2][4][4];
    #pragma unroll
    for (int a = 0; a < 2; ++a)
        #pragma unroll
        for (int b = 0; b < 4; ++b)
            #pragma unroll
            for (int c = 0; c < 4; ++c) acc[a][b][c] = 0.f;

    const int lrow = lane & 15;              // ldmatrix row-select
    const int lkof = (lane >> 4) * 8;        // 0 or 8 halves

    auto load_stage = [&](int s, int kt) {
        const int k0 = kt * BK;
        char* as = smem + s * STB;
        char* bs = as + ABYTES;
        #pragma unroll
        for (int i = 0; i < 2; ++i) {
            int id = tid + NTHREADS * i;
            int row = id >> 3, ch = id & 7;                 // 128 rows x 8 16B-chunks
            cpasync16(as + (row * ALD + ch * 8) * 2,
                      A + (mbase + row) * KDIM + k0 + ch * 8);
            cpasync16(bs + (row * ALD + ch * 8) * 2,
                      Bt + (size_t)(nbase + row) * KDIM + k0 + ch * 8);
        }
    };

    auto compute = [&](int s) {
        const char* as = smem + s * STB;
        const uint32_t a_u32 = smem_u32(as);
        const uint32_t b_u32 = a_u32 + ABYTES;
        #pragma unroll
        for (int ks = 0; ks < 4; ++ks) {
            const int kh = ks * 16;
            uint32_t af[2][4];
            #pragma unroll
            for (int mi = 0; mi < 2; ++mi) {
                int row = wm * 32 + mi * 16 + lrow;
                ldsm_x4(af[mi][0], af[mi][1], af[mi][2], af[mi][3],
                        a_u32 + (row * ALD + kh + lkof) * 2);
            }
            uint32_t bf[4][2];
            #pragma unroll
            for (int np = 0; np < 2; ++np) {
                int row = wn * 32 + np * 16 + lrow;
                ldsm_x4(bf[2 * np][0], bf[2 * np + 1][0],
                        bf[2 * np][1], bf[2 * np + 1][1],
                        b_u32 + (row * ALD + kh + lkof) * 2);
            }
            #pragma unroll
            for (int mi = 0; mi < 2; ++mi)
                #pragma unroll
                for (int ni = 0; ni < 4; ++ni)
                    mma16816(acc[mi][ni][0], acc[mi][ni][1], acc[mi][ni][2], acc[mi][ni][3],
                             af[mi][0], af[mi][1], af[mi][2], af[mi][3],
                             bf[ni][0], bf[ni][1]);
        }
    };

    load_stage(0, 0); cp_commit();
    load_stage(1, 1); cp_commit();

    #pragma unroll
    for (int kt = 0; kt < KTILES; ++kt) {
        cp_wait1();
        __syncthreads();
        if (kt + 2 < KTILES) load_stage((kt + 2) % 3, kt + 2);
        cp_commit();
        compute(kt % 3);
    }

    // ------------------------------ epilogue --------------------------------
    if (MODE == 1) {
        #pragma unroll
        for (int mi = 0; mi < 2; ++mi) {
            int r0 = wm * 32 + mi * 16 + (lane >> 2);
            #pragma unroll
            for (int ni = 0; ni < 4; ++ni) {
                int c0 = wn * 32 + ni * 8 + ((lane & 3) << 1);
                int gc = nbase + c0;
                if (mtile == 0) {
                    g_L1[r0 * NDIM + gc]           = acc[mi][ni][0];
                    g_L1[r0 * NDIM + gc + 1]       = acc[mi][ni][1];
                    g_L1[(r0 + 8) * NDIM + gc]     = acc[mi][ni][2];
                    g_L1[(r0 + 8) * NDIM + gc + 1] = acc[mi][ni][3];
                }
                float bb0 = bias[gc], bb1 = bias[gc + 1];
                float v0 = fmaxf(acc[mi][ni][0] + bb0, 0.f);
                float v1 = fmaxf(acc[mi][ni][1] + bb1, 0.f);
                float v2 = fmaxf(acc[mi][ni][2] + bb0, 0.f);
                float v3 = fmaxf(acc[mi][ni][3] + bb1, 0.f);
                *reinterpret_cast<__half2*>(g_H1 + (mbase + r0) * NDIM + gc)     = __floats2half2_rn(v0, v1);
                *reinterpret_cast<__half2*>(g_H1 + (mbase + r0 + 8) * NDIM + gc) = __floats2half2_rn(v2, v3);
            }
        }
    } else {
        float cs0[4], cs1[4];
        #pragma unroll
        for (int ni = 0; ni < 4; ++ni) { cs0[ni] = 0.f; cs1[ni] = 0.f; }
        #pragma unroll
        for (int mi = 0; mi < 2; ++mi) {
            int r0 = wm * 32 + mi * 16 + (lane >> 2);
            #pragma unroll
            for (int ni = 0; ni < 4; ++ni) {
                int c0 = wn * 32 + ni * 8 + ((lane & 3) << 1);
                int gc = nbase + c0;
                if (mtile == 0) {
                    g_L2[r0 * NDIM + gc]           = acc[mi][ni][0];
                    g_L2[r0 * NDIM + gc + 1]       = acc[mi][ni][1];
                    g_L2[(r0 + 8) * NDIM + gc]     = acc[mi][ni][2];
                    g_L2[(r0 + 8) * NDIM + gc + 1] = acc[mi][ni][3];
                }
                float bb0 = bias[gc], bb1 = bias[gc + 1];
                cs0[ni] += fmaxf(acc[mi][ni][0] + bb0, 0.f) + fmaxf(acc[mi][ni][2] + bb0, 0.f);
                cs1[ni] += fmaxf(acc[mi][ni][1] + bb1, 0.f) + fmaxf(acc[mi][ni][3] + bb1, 0.f);
            }
        }
        #pragma unroll
        for (int ni = 0; ni < 4; ++ni) {
            #pragma unroll
            for (int o = 4; o <= 16; o <<= 1) {
                cs0[ni] += __shfl_xor_sync(0xffffffffu, cs0[ni], o);
                cs1[ni] += __shfl_xor_sync(0xffffffffu, cs1[ni], o);
            }
        }
        __syncthreads();
        float* cs = reinterpret_cast<float*>(smem);
        if (tid < BN) cs[tid] = 0.f;
        __syncthreads();
        if ((lane >> 2) == 0) {
            #pragma unroll
            for (int ni = 0; ni < 4; ++ni) {
                int c0 = wn * 32 + ni * 8 + ((lane & 3) << 1);
                atomicAdd(&cs[c0],     cs0[ni]);
                atomicAdd(&cs[c0 + 1], cs1[ni]);
            }
        }
        __syncthreads();
        if (tid < BN) g_pool[(size_t)mtile * NDIM + nbase + tid] = cs[tid];
    }
}

// ------------------------------- graph-0 fixups (parallel) ------------------
__global__ void fixup1_kernel(const float* __restrict__ b1) {
    int c = blockIdx.x;                  // 512 columns
    int r = threadIdx.x;                 // 128 rows
    float v = g_L1[r * NDIM + c];
    __shared__ float sred[4];
    float s = v;
    #pragma unroll
    for (int o = 16; o; o >>= 1) s += __shfl_xor_sync(0xffffffffu, s, o);
    if ((r & 31) == 0) sred[r >> 5] = s;
    __syncthreads();
    float S = sred[0] + sred[1] + sred[2] + sred[3];
    float out = (S + v) * (1.f / 129.f) + b1[c];
    g_H1[(size_t)r * NDIM + c] = __float2half(out > 0.f ? out : 0.f);
}

__global__ void fixup2_kernel(const float* __restrict__ b2) {
    int c = blockIdx.x;
    int r = threadIdx.x;
    float v = g_L2[r * NDIM + c];
    __shared__ float sred[4];
    float s = v;
    #pragma unroll
    for (int o = 16; o; o >>= 1) s += __shfl_xor_sync(0xffffffffu, s, o);
    if ((r & 31) == 0) sred[r >> 5] = s;
    __syncthreads();
    float S = sred[0] + sred[1] + sred[2] + sred[3];
    float val = (S + v) * (1.f / 129.f) + b2[c];
    float rel = val > 0.f ? val : 0.f;
    #pragma unroll
    for (int o = 16; o; o >>= 1) rel += __shfl_xor_sync(0xffffffffu, rel, o);
    if ((r & 31) == 0) sred[r >> 5] = rel;
    __syncthreads();
    if (r == 0) g_pool[c] = sred[0] + sred[1] + sred[2] + sred[3];
}

// ------------------------------- final projection ---------------------------
// 4 graphs per block; Wc staged in smem (coalesced).
__global__ void final_kernel(float* __restrict__ out) {
    __shared__ float wc[KDIM * OUTD];    // 20 KB
    int tid = threadIdx.x;
    for (int i = tid; i < KDIM * OUTD; i += 320) wc[i] = g_Wc[i];
    __syncthreads();
    int c = tid >> 5, lane = tid & 31;   // 10 warps: one output column each
    #pragma unroll
    for (int gg = 0; gg < 4; ++gg) {
        int g = blockIdx.x * 4 + gg;
        float a = 0.f;
        for (int k = lane; k < KDIM; k += 32)
            a += g_pool[(size_t)g * NDIM + k] * wc[k * OUTD + c];
        #pragma unroll
        for (int o = 16; o; o >>= 1) a += __shfl_xor_sync(0xffffffffu, a, o);
        if (lane == 0) out[g * OUTD + c] = a * (1.f / (float)GSIZE) + g_bc[c];
    }
}

// ------------------------------- launch -------------------------------------
extern "C" void kernel_launch(void* const* d_in, const int* in_sizes, int n_in,
                              void* d_out, int out_size) {
    const float* x    = (const float*)d_in[0];
    const float* W1   = (const float*)d_in[1];
    const float* b1   = (const float*)d_in[2];
    const float* W2   = (const float*)d_in[3];
    const float* b2   = (const float*)d_in[4];
    const float* W3   = (const float*)d_in[5];
    const float* b3   = (const float*)d_in[6];
    const float* Wlin = (const float*)d_in[7];
    const float* blin = (const float*)d_in[8];
    float* out = (float*)d_out;

    cudaFuncSetAttribute(gemm_kernel<1>, cudaFuncAttributeMaxDynamicSharedMemorySize, SMEM_TOTAL);
    cudaFuncSetAttribute(gemm_kernel<2>, cudaFuncAttributeMaxDynamicSharedMemorySize, SMEM_TOTAL);

    dim3 grid(NDIM / BN, NROWS / BM);    // (4, 512)

    conv_x_kernel<<<(int)(((size_t)NROWS * KDIM) / (256 * 8)), 256>>>(x);   // 1
    convT_w_kernel<<<dim3(16, 16, 2), dim3(32, 8)>>>(W1, W2);               // 2
    gemm_kernel<1><<<grid, NTHREADS, SMEM_TOTAL>>>(b1);                     // 3
    fixup1_kernel<<<NDIM, GSIZE>>>(b1);                                     // 4
    wcbc_kernel<<<65, 256>>>(W3, Wlin, b3, blin);                           // 5
    gemm_kernel<2><<<grid, NTHREADS, SMEM_TOTAL>>>(b2);                     // 6  <- ncu
    fixup2_kernel<<<NDIM, GSIZE>>>(b2);                                     // 7
    final_kernel<<<NGRAPH / 4, 320>>>(out);                                 // 8
}

// round 16
// speedup vs baseline: 1.5927x; 1.4630x over previous
#include <cuda_runtime.h>
#include <cuda_fp16.h>
#include <cstdint>

// ---------------------------------------------------------------------------
// GCN_simple: layer3+meanpool collapse analytically; layers 1-2 are dense
// GEMMs (identity propagation except graph 0, fixed by parallel fixups).
// mma.sync HMMA pipeline (tcgen05 rejected by compute_103 virtual target).
// R13: controlled re-bench. Everything up to and including gemm2 is the exact
// R8 binary (299.7us proven). Only the post-gemm2 tail is improved: wc+bc
// merged with smem-staged Wlin (old wc measured 15.6us, uncoalesced), final
// smem-stages Wc and does 4 graphs/block.
// ---------------------------------------------------------------------------

#define NROWS 65536      // BATCH * N_NODES
#define KDIM  512
#define NDIM  512
#define NGRAPH 512
#define GSIZE  128
#define OUTD   10

#define BM 128
#define BN 128
#define BK 64
#define KTILES (KDIM / BK)   // 8
#define ALD 72               // smem row pitch in halves (64 + 8 pad)

#define ABYTES (BM * ALD * 2)        // 18432
#define BBYTES (BN * ALD * 2)        // 18432
#define STB (ABYTES + BBYTES)        // 36864
#define SMEM_TOTAL (3 * STB)         // 110592

#define NTHREADS 512

// ------------------------------- device scratch -----------------------------
__device__ __half g_Xh[(size_t)NROWS * KDIM];
__device__ __half g_H1[(size_t)NROWS * KDIM];
__device__ __half g_W1t[KDIM * NDIM];   // W1^T: [n][k] fp16
__device__ __half g_W2t[KDIM * NDIM];
__device__ float  g_pool[NGRAPH * NDIM];
__device__ float  g_L1[GSIZE * NDIM];
__device__ float  g_L2[GSIZE * NDIM];
__device__ float  g_Wc[KDIM * OUTD];
__device__ float  g_bc[OUTD];

// ------------------------------- helpers ------------------------------------
__device__ __forceinline__ void cpasync16(void* smem_ptr, const void* gmem_ptr) {
    uint32_t s = (uint32_t)__cvta_generic_to_shared(smem_ptr);
    asm volatile("cp.async.cg.shared.global [%0], [%1], 16;\n" :: "r"(s), "l"(gmem_ptr));
}
__device__ __forceinline__ void cp_commit() {
    asm volatile("cp.async.commit_group;\n" ::: "memory");
}
__device__ __forceinline__ void cp_wait1() {
    asm volatile("cp.async.wait_group 1;\n" ::: "memory");
}
__device__ __forceinline__ void mma16816(float& c0, float& c1, float& c2, float& c3,
                                         uint32_t a0, uint32_t a1, uint32_t a2, uint32_t a3,
                                         uint32_t b0, uint32_t b1) {
    asm volatile(
        "mma.sync.aligned.m16n8k16.row.col.f32.f16.f16.f32 "
        "{%0,%1,%2,%3}, {%4,%5,%6,%7}, {%8,%9}, {%0,%1,%2,%3};\n"
        : "+f"(c0), "+f"(c1), "+f"(c2), "+f"(c3)
        : "r"(a0), "r"(a1), "r"(a2), "r"(a3), "r"(b0), "r"(b1));
}
__device__ __forceinline__ void ldsm_x4(uint32_t& r0, uint32_t& r1, uint32_t& r2, uint32_t& r3,
                                        uint32_t saddr) {
    asm volatile("ldmatrix.sync.aligned.m8n8.x4.shared.b16 {%0,%1,%2,%3}, [%4];"
                 : "=r"(r0), "=r"(r1), "=r"(r2), "=r"(r3) : "r"(saddr));
}
__device__ __forceinline__ uint32_t smem_u32(const void* p) {
    return (uint32_t)__cvta_generic_to_shared(p);
}

// ------------------------------- setup kernels ------------------------------
__global__ void conv_x_kernel(const float* __restrict__ x) {
    size_t i = ((size_t)blockIdx.x * blockDim.x + threadIdx.x) * 8;
    float4 v0 = *reinterpret_cast<const float4*>(x + i);
    float4 v1 = *reinterpret_cast<const float4*>(x + i + 4);
    __half2 h0 = __floats2half2_rn(v0.x, v0.y);
    __half2 h1 = __floats2half2_rn(v0.z, v0.w);
    __half2 h2 = __floats2half2_rn(v1.x, v1.y);
    __half2 h3 = __floats2half2_rn(v1.z, v1.w);
    uint4 packed = make_uint4(*reinterpret_cast<uint32_t*>(&h0), *reinterpret_cast<uint32_t*>(&h1),
                              *reinterpret_cast<uint32_t*>(&h2), *reinterpret_cast<uint32_t*>(&h3));
    *reinterpret_cast<uint4*>(g_Xh + i) = packed;
}

// out[n][k] = (half) W[k][n]
__global__ void convT_w_kernel(const float* __restrict__ W, int which) {
    __shared__ float t[32][33];
    __half* out = which ? g_W2t : g_W1t;
    int bx = blockIdx.x * 32, by = blockIdx.y * 32;
    #pragma unroll
    for (int i = 0; i < 32; i += 8)
        t[threadIdx.y + i][threadIdx.x] = W[(size_t)(by + threadIdx.y + i) * NDIM + bx + threadIdx.x];
    __syncthreads();
    #pragma unroll
    for (int i = 0; i < 32; i += 8)
        out[(size_t)(bx + threadIdx.y + i) * KDIM + by + threadIdx.x] =
            __float2half(t[threadIdx.x][threadIdx.y + i]);
}

// Blocks 0..63: Wc[k][c] = sum_j W3[k][j]*Wlin[j][c] for 8 k-rows per block.
// Block 64:    bc[c] = sum_j b3[j]*Wlin[j][c] + blin[c].
__global__ void wcbc_kernel(const float* __restrict__ W3, const float* __restrict__ Wlin,
                            const float* __restrict__ b3, const float* __restrict__ blin) {
    __shared__ float wl[KDIM * OUTD];    // 20 KB, coalesced load
    int tid = threadIdx.x;
    for (int i = tid; i < KDIM * OUTD; i += 256) wl[i] = Wlin[i];
    __syncthreads();
    int warp = tid >> 5, lane = tid & 31;
    if (blockIdx.x < 64) {
        int k = blockIdx.x * 8 + warp;
        float acc[OUTD];
        #pragma unroll
        for (int c = 0; c < OUTD; ++c) acc[c] = 0.f;
        for (int j = lane; j < KDIM; j += 32) {
            float a = W3[(size_t)k * KDIM + j];
            #pragma unroll
            for (int c = 0; c < OUTD; ++c) acc[c] += a * wl[j * OUTD + c];
        }
        #pragma unroll
        for (int c = 0; c < OUTD; ++c)
            #pragma unroll
            for (int o = 16; o; o >>= 1) acc[c] += __shfl_xor_sync(0xffffffffu, acc[c], o);
        if (lane < OUTD) g_Wc[k * OUTD + lane] = acc[lane];  // acc[] identical on all lanes
    } else if (warp == 0) {
        float acc[OUTD];
        #pragma unroll
        for (int c = 0; c < OUTD; ++c) acc[c] = 0.f;
        for (int j = lane; j < KDIM; j += 32) {
            float a = b3[j];
            #pragma unroll
            for (int c = 0; c < OUTD; ++c) acc[c] += a * wl[j * OUTD + c];
        }
        #pragma unroll
        for (int c = 0; c < OUTD; ++c)
            #pragma unroll
            for (int o = 16; o; o >>= 1) acc[c] += __shfl_xor_sync(0xffffffffu, acc[c], o);
        if (lane < OUTD) g_bc[lane] = acc[lane] + blin[lane];
    }
}

// ------------------------------- main GEMMs (R8-proven, unchanged) ----------
// 512 threads, 16 warps as 4x4 grid of 32x32 warp tiles over 128x128 CTA tile.
// MODE 1: H1 = relu(Xh @ W1 + b1); mtile 0 raw acc -> g_L1.
// MODE 2: pool[g] = colsum(relu(H1 @ W2 + b2)); mtile 0 raw acc -> g_L2.
template <int MODE>
__global__ void __launch_bounds__(NTHREADS, 2) gemm_kernel(const float* __restrict__ bias) {
    extern __shared__ char smem[];
    const int tid  = threadIdx.x;
    const int lane = tid & 31;
    const int warp = tid >> 5;
    const int wm = warp >> 2;                // 0..3  (32-row strip)
    const int wn = warp & 3;                 // 0..3  (32-col strip)
    const int ntile = blockIdx.x;
    const int mtile = blockIdx.y;
    const size_t mbase = (size_t)mtile * BM;
    const int nbase = ntile * BN;

    const __half* __restrict__ A  = (MODE == 1) ? g_Xh  : g_H1;
    const __half* __restrict__ Bt = (MODE == 1) ? g_W1t : g_W2t;

    float acc[2][4][4];
    #pragma unroll
    for (int a = 0; a < 2; ++a)
        #pragma unroll
        for (int b = 0; b < 4; ++b)
            #pragma unroll
            for (int c = 0; c < 4; ++c) acc[a][b][c] = 0.f;

    const int lrow = lane & 15;              // ldmatrix row-select
    const int lkof = (lane >> 4) * 8;        // 0 or 8 halves

    auto load_stage = [&](int s, int kt) {
        const int k0 = kt * BK;
        char* as = smem + s * STB;
        char* bs = as + ABYTES;
        #pragma unroll
        for (int i = 0; i < 2; ++i) {
            int id = tid + NTHREADS * i;
            int row = id >> 3, ch = id & 7;                 // 128 rows x 8 16B-chunks
            cpasync16(as + (row * ALD + ch * 8) * 2,
                      A + (mbase + row) * KDIM + k0 + ch * 8);
            cpasync16(bs + (row * ALD + ch * 8) * 2,
                      Bt + (size_t)(nbase + row) * KDIM + k0 + ch * 8);
        }
    };

    auto compute = [&](int s) {
        const char* as = smem + s * STB;
        const uint32_t a_u32 = smem_u32(as);
        const uint32_t b_u32 = a_u32 + ABYTES;
        #pragma unroll
        for (int ks = 0; ks < 4; ++ks) {
            const int kh = ks * 16;
            uint32_t af[2][4];
            #pragma unroll
            for (int mi = 0; mi < 2; ++mi) {
                int row = wm * 32 + mi * 16 + lrow;
                ldsm_x4(af[mi][0], af[mi][1], af[mi][2], af[mi][3],
                        a_u32 + (row * ALD + kh + lkof) * 2);
            }
            uint32_t bf[4][2];
            #pragma unroll
            for (int np = 0; np < 2; ++np) {
                int row = wn * 32 + np * 16 + lrow;
                ldsm_x4(bf[2 * np][0], bf[2 * np + 1][0],
                        bf[2 * np][1], bf[2 * np + 1][1],
                        b_u32 + (row * ALD + kh + lkof) * 2);
            }
            #pragma unroll
            for (int mi = 0; mi < 2; ++mi)
                #pragma unroll
                for (int ni = 0; ni < 4; ++ni)
                    mma16816(acc[mi][ni][0], acc[mi][ni][1], acc[mi][ni][2], acc[mi][ni][3],
                             af[mi][0], af[mi][1], af[mi][2], af[mi][3],
                             bf[ni][0], bf[ni][1]);
        }
    };

    load_stage(0, 0); cp_commit();
    load_stage(1, 1); cp_commit();

    #pragma unroll
    for (int kt = 0; kt < KTILES; ++kt) {
        cp_wait1();
        __syncthreads();
        if (kt + 2 < KTILES) load_stage((kt + 2) % 3, kt + 2);
        cp_commit();
        compute(kt % 3);
    }

    // ------------------------------ epilogue --------------------------------
    if (MODE == 1) {
        #pragma unroll
        for (int mi = 0; mi < 2; ++mi) {
            int r0 = wm * 32 + mi * 16 + (lane >> 2);
            #pragma unroll
            for (int ni = 0; ni < 4; ++ni) {
                int c0 = wn * 32 + ni * 8 + ((lane & 3) << 1);
                int gc = nbase + c0;
                if (mtile == 0) {
                    g_L1[r0 * NDIM + gc]           = acc[mi][ni][0];
                    g_L1[r0 * NDIM + gc + 1]       = acc[mi][ni][1];
                    g_L1[(r0 + 8) * NDIM + gc]     = acc[mi][ni][2];
                    g_L1[(r0 + 8) * NDIM + gc + 1] = acc[mi][ni][3];
                }
                float bb0 = bias[gc], bb1 = bias[gc + 1];
                float v0 = fmaxf(acc[mi][ni][0] + bb0, 0.f);
                float v1 = fmaxf(acc[mi][ni][1] + bb1, 0.f);
                float v2 = fmaxf(acc[mi][ni][2] + bb0, 0.f);
                float v3 = fmaxf(acc[mi][ni][3] + bb1, 0.f);
                *reinterpret_cast<__half2*>(g_H1 + (mbase + r0) * NDIM + gc)     = __floats2half2_rn(v0, v1);
                *reinterpret_cast<__half2*>(g_H1 + (mbase + r0 + 8) * NDIM + gc) = __floats2half2_rn(v2, v3);
            }
        }
    } else {
        float cs0[4], cs1[4];
        #pragma unroll
        for (int ni = 0; ni < 4; ++ni) { cs0[ni] = 0.f; cs1[ni] = 0.f; }
        #pragma unroll
        for (int mi = 0; mi < 2; ++mi) {
            int r0 = wm * 32 + mi * 16 + (lane >> 2);
            #pragma unroll
            for (int ni = 0; ni < 4; ++ni) {
                int c0 = wn * 32 + ni * 8 + ((lane & 3) << 1);
                int gc = nbase + c0;
                if (mtile == 0) {
                    g_L2[r0 * NDIM + gc]           = acc[mi][ni][0];
                    g_L2[r0 * NDIM + gc + 1]       = acc[mi][ni][1];
                    g_L2[(r0 + 8) * NDIM + gc]     = acc[mi][ni][2];
                    g_L2[(r0 + 8) * NDIM + gc + 1] = acc[mi][ni][3];
                }
                float bb0 = bias[gc], bb1 = bias[gc + 1];
                cs0[ni] += fmaxf(acc[mi][ni][0] + bb0, 0.f) + fmaxf(acc[mi][ni][2] + bb0, 0.f);
                cs1[ni] += fmaxf(acc[mi][ni][1] + bb1, 0.f) + fmaxf(acc[mi][ni][3] + bb1, 0.f);
            }
        }
        #pragma unroll
        for (int ni = 0; ni < 4; ++ni) {
            #pragma unroll
            for (int o = 4; o <= 16; o <<= 1) {
                cs0[ni] += __shfl_xor_sync(0xffffffffu, cs0[ni], o);
                cs1[ni] += __shfl_xor_sync(0xffffffffu, cs1[ni], o);
            }
        }
        __syncthreads();
        float* cs = reinterpret_cast<float*>(smem);
        if (tid < BN) cs[tid] = 0.f;
        __syncthreads();
        if ((lane >> 2) == 0) {
            #pragma unroll
            for (int ni = 0; ni < 4; ++ni) {
                int c0 = wn * 32 + ni * 8 + ((lane & 3) << 1);
                atomicAdd(&cs[c0],     cs0[ni]);
                atomicAdd(&cs[c0 + 1], cs1[ni]);
            }
        }
        __syncthreads();
        if (tid < BN) g_pool[(size_t)mtile * NDIM + nbase + tid] = cs[tid];
    }
}

// ------------------------------- graph-0 fixups (parallel) ------------------
__global__ void fixup1_kernel(const float* __restrict__ b1) {
    int c = blockIdx.x;                  // 512 columns
    int r = threadIdx.x;                 // 128 rows
    float v = g_L1[r * NDIM + c];
    __shared__ float sred[4];
    float s = v;
    #pragma unroll
    for (int o = 16; o; o >>= 1) s += __shfl_xor_sync(0xffffffffu, s, o);
    if ((r & 31) == 0) sred[r >> 5] = s;
    __syncthreads();
    float S = sred[0] + sred[1] + sred[2] + sred[3];
    float out = (S + v) * (1.f / 129.f) + b1[c];
    g_H1[(size_t)r * NDIM + c] = __float2half(out > 0.f ? out : 0.f);
}

__global__ void fixup2_kernel(const float* __restrict__ b2) {
    int c = blockIdx.x;
    int r = threadIdx.x;
    float v = g_L2[r * NDIM + c];
    __shared__ float sred[4];
    float s = v;
    #pragma unroll
    for (int o = 16; o; o >>= 1) s += __shfl_xor_sync(0xffffffffu, s, o);
    if ((r & 31) == 0) sred[r >> 5] = s;
    __syncthreads();
    float S = sred[0] + sred[1] + sred[2] + sred[3];
    float val = (S + v) * (1.f / 129.f) + b2[c];
    float rel = val > 0.f ? val : 0.f;
    #pragma unroll
    for (int o = 16; o; o >>= 1) rel += __shfl_xor_sync(0xffffffffu, rel, o);
    if ((r & 31) == 0) sred[r >> 5] = rel;
    __syncthreads();
    if (r == 0) g_pool[c] = sred[0] + sred[1] + sred[2] + sred[3];
}

// ------------------------------- final projection ---------------------------
// 4 graphs per block; Wc staged in smem (coalesced).
__global__ void final_kernel(float* __restrict__ out) {
    __shared__ float wc[KDIM * OUTD];    // 20 KB
    int tid = threadIdx.x;
    for (int i = tid; i < KDIM * OUTD; i += 320) wc[i] = g_Wc[i];
    __syncthreads();
    int c = tid >> 5, lane = tid & 31;   // 10 warps: one output column each
    #pragma unroll
    for (int gg = 0; gg < 4; ++gg) {
        int g = blockIdx.x * 4 + gg;
        float a = 0.f;
        for (int k = lane; k < KDIM; k += 32)
            a += g_pool[(size_t)g * NDIM + k] * wc[k * OUTD + c];
        #pragma unroll
        for (int o = 16; o; o >>= 1) a += __shfl_xor_sync(0xffffffffu, a, o);
        if (lane == 0) out[g * OUTD + c] = a * (1.f / (float)GSIZE) + g_bc[c];
    }
}

// ------------------------------- launch (R8 order; tail kernels swapped) ----
extern "C" void kernel_launch(void* const* d_in, const int* in_sizes, int n_in,
                              void* d_out, int out_size) {
    const float* x    = (const float*)d_in[0];
    const float* W1   = (const float*)d_in[1];
    const float* b1   = (const float*)d_in[2];
    const float* W2   = (const float*)d_in[3];
    const float* b2   = (const float*)d_in[4];
    const float* W3   = (const float*)d_in[5];
    const float* b3   = (const float*)d_in[6];
    const float* Wlin = (const float*)d_in[7];
    const float* blin = (const float*)d_in[8];
    float* out = (float*)d_out;

    cudaFuncSetAttribute(gemm_kernel<1>, cudaFuncAttributeMaxDynamicSharedMemorySize, SMEM_TOTAL);
    cudaFuncSetAttribute(gemm_kernel<2>, cudaFuncAttributeMaxDynamicSharedMemorySize, SMEM_TOTAL);

    dim3 grid(NDIM / BN, NROWS / BM);    // (4, 512)

    conv_x_kernel<<<(int)(((size_t)NROWS * KDIM) / (256 * 8)), 256>>>(x);   // 1
    convT_w_kernel<<<dim3(16, 16), dim3(32, 8)>>>(W1, 0);                   // 2
    convT_w_kernel<<<dim3(16, 16), dim3(32, 8)>>>(W2, 1);                   // 3
    gemm_kernel<1><<<grid, NTHREADS, SMEM_TOTAL>>>(b1);                     // 4
    fixup1_kernel<<<NDIM, GSIZE>>>(b1);                                     // 5
    gemm_kernel<2><<<grid, NTHREADS, SMEM_TOTAL>>>(b2);                     // 6
    wcbc_kernel<<<65, 256>>>(W3, Wlin, b3, blin);                           // 7
    fixup2_kernel<<<NDIM, GSIZE>>>(b2);                                     // 8
    final_kernel<<<NGRAPH / 4, 320>>>(out);                                 // 9
}